// round 2
// baseline (speedup 1.0000x reference)
#include <cuda_runtime.h>
#include <cuda_bf16.h>
#include <math.h>

// ---- Physical constants, folded at compile time (double precision, cast once) ----
namespace mk {
constexpr double R_      = 3.0 * 0.0254;                 // wheel radius
constexpr double LSUM    = 0.129907 + 0.095724;          // L_X + L_Y
constexpr double G_      = 13.7;
constexpr double MASS_   = 12.0;
constexpr double MOI_    = MASS_ * (12.0 * 0.0254) * (12.0 * 0.0254) / 6.0;

constexpr float INV_R = (float)(1.0 / R_);
constexpr float L_R   = (float)(LSUM / R_);
constexpr float T_DUTY = (float)(0.193 * G_);
constexpr float T_VEL  = (float)(G_ * 0.000304 * G_);
constexpr float T_FRIC = (float)(0.00317 * G_);
constexpr float K_XY = (float)(1.0 / (4.0 * R_ * MASS_));
constexpr float K_W  = (float)(1.0 / (4.0 * LSUM * R_ * MOI_));
constexpr float EPS  = 0.01f;
}

__device__ __forceinline__ void mecanum_row(
    float theta, float vx, float vy, float wz,
    float u0, float u1, float u2,
    float& ax, float& ay, float& aw)
{
    float st, ct;
    sincosf(theta, &st, &ct);

    // local velocity (rotation by -theta)
    float lvx =  ct * vx + st * vy;
    float lvy = -st * vx + ct * vy;

    // wheel velocities
    float p = mk::INV_R * (lvx + lvy);
    float m = mk::INV_R * (lvx - lvy);
    float lz = mk::L_R * wz;
    float w0 = m - lz;
    float w1 = p + lz;
    float w2 = p - lz;
    float w3 = m + lz;

    // motor duty
    float m0 = u0 - u1 - u2;
    float m1 = u0 + u1 + u2;
    float m2 = u0 + u1 - u2;
    float m3 = u0 - u1 + u2;

    // wheel torque
    float ss0 = w0 * rsqrtf(w0 * w0 + mk::EPS);
    float ss1 = w1 * rsqrtf(w1 * w1 + mk::EPS);
    float ss2 = w2 * rsqrtf(w2 * w2 + mk::EPS);
    float ss3 = w3 * rsqrtf(w3 * w3 + mk::EPS);
    float t0 = mk::T_DUTY * m0 - mk::T_VEL * w0 - mk::T_FRIC * ss0;
    float t1 = mk::T_DUTY * m1 - mk::T_VEL * w1 - mk::T_FRIC * ss1;
    float t2 = mk::T_DUTY * m2 - mk::T_VEL * w2 - mk::T_FRIC * ss2;
    float t3 = mk::T_DUTY * m3 - mk::T_VEL * w3 - mk::T_FRIC * ss3;

    // local acceleration (analytic pinv of the 4x3 wheel matrix)
    float la0 = mk::K_XY * ( t0 + t1 + t2 + t3);
    float la1 = mk::K_XY * (-t0 + t1 + t2 - t3);
    float la2 = mk::K_W  * (-t0 + t1 - t2 + t3);

    // rotate back by +theta (A^T)
    ax = ct * la0 - st * la1;
    ay = st * la0 + ct * la1;
    aw = la2;
}

// ---- Shared-memory staged kernel ----
// Block = 256 threads, 1024 rows. Each thread owns a "group" of 4 rows.
// Global <-> smem transfers are float4 with lane stride 16B (ideal coalescing).
// Smem layout uses ODD strides (25 floats per 24-float state group, 13 per
// 12-float ctrl group) so every compute-phase LDS/STS is bank-conflict-free
// (odd stride is a permutation of banks across the 32 lanes).
constexpr int THREADS       = 256;
constexpr int ROWS_PER_BLK  = 4 * THREADS;   // 1024
constexpr int SSTRIDE       = 25;            // 24 state floats + 1 pad
constexpr int CSTRIDE       = 13;            // 12 ctrl  floats + 1 pad

__global__ void __launch_bounds__(THREADS)
mecanum_smem_kernel(const float4* __restrict__ st4,
                    const float4* __restrict__ cd4,
                    float4* __restrict__ out4,
                    int B)
{
    __shared__ float s_s[THREADS * SSTRIDE];   // 25.0 KB (state, reused for output)
    __shared__ float s_c[THREADS * CSTRIDE];   // 13.0 KB (control)

    const int  t  = threadIdx.x;
    const long long row0 = (long long)blockIdx.x * ROWS_PER_BLK;
    const long long nsf4 = (long long)B * 6 / 4;   // total state/out float4s
    const long long ncf4 = (long long)B * 3 / 4;   // total ctrl float4s
    const long long sb   = (long long)blockIdx.x * (ROWS_PER_BLK * 6 / 4); // 1536*b
    const long long cb   = (long long)blockIdx.x * (ROWS_PER_BLK * 3 / 4); // 768*b

    // ---- Phase 1: coalesced global -> smem ----
#pragma unroll
    for (int k = 0; k < 6; k++) {
        long long f = sb + t + THREADS * k;
        if (f < nsf4) {
            float4 v = st4[f];
            int lf   = t + THREADS * k;        // local float4 index
            int g    = lf / 6;                 // group (thread) that owns it
            int off  = (lf % 6) * 4;           // float offset within group
            int base = g * SSTRIDE + off;
            s_s[base + 0] = v.x; s_s[base + 1] = v.y;
            s_s[base + 2] = v.z; s_s[base + 3] = v.w;
        }
    }
#pragma unroll
    for (int k = 0; k < 3; k++) {
        long long f = cb + t + THREADS * k;
        if (f < ncf4) {
            float4 v = cd4[f];
            int lf   = t + THREADS * k;
            int g    = lf / 3;
            int off  = (lf % 3) * 4;
            int base = g * CSTRIDE + off;
            s_c[base + 0] = v.x; s_c[base + 1] = v.y;
            s_c[base + 2] = v.z; s_c[base + 3] = v.w;
        }
    }
    __syncthreads();

    // ---- Phase 2: compute 4 rows from this thread's own group, in-place ----
    const int sbase = t * SSTRIDE;
    const int cbase = t * CSTRIDE;
#pragma unroll
    for (int r = 0; r < 4; r++) {
        long long row = row0 + 4LL * t + r;
        if (row < B) {
            int so = sbase + 6 * r;
            int co = cbase + 3 * r;
            float theta = s_s[so + 2];
            float vx = s_s[so + 3], vy = s_s[so + 4], wz = s_s[so + 5];
            float ax, ay, aw;
            mecanum_row(theta, vx, vy, wz,
                        s_c[co + 0], s_c[co + 1], s_c[co + 2],
                        ax, ay, aw);
            s_s[so + 0] = vx; s_s[so + 1] = vy; s_s[so + 2] = wz;
            s_s[so + 3] = ax; s_s[so + 4] = ay; s_s[so + 5] = aw;
        }
    }
    __syncthreads();

    // ---- Phase 3: coalesced smem -> global ----
#pragma unroll
    for (int k = 0; k < 6; k++) {
        long long f = sb + t + THREADS * k;
        if (f < nsf4) {
            int lf   = t + THREADS * k;
            int g    = lf / 6;
            int off  = (lf % 6) * 4;
            int base = g * SSTRIDE + off;
            float4 v;
            v.x = s_s[base + 0]; v.y = s_s[base + 1];
            v.z = s_s[base + 2]; v.w = s_s[base + 3];
            out4[f] = v;
        }
    }
}

// Scalar fallback (any B, used only if B % 4 != 0)
__global__ void __launch_bounds__(256)
mecanum1_kernel(const float* __restrict__ state,
                const float* __restrict__ ctrl,
                float* __restrict__ out,
                int B)
{
    int i = blockIdx.x * blockDim.x + threadIdx.x;
    if (i >= B) return;
    const float* s = state + 6 * (size_t)i;
    const float* u = ctrl + 3 * (size_t)i;
    float* o = out + 6 * (size_t)i;
    float ax, ay, aw;
    mecanum_row(s[2], s[3], s[4], s[5], u[0], u[1], u[2], ax, ay, aw);
    o[0] = s[3]; o[1] = s[4]; o[2] = s[5];
    o[3] = ax;   o[4] = ay;   o[5] = aw;
}

extern "C" void kernel_launch(void* const* d_in, const int* in_sizes, int n_in,
                              void* d_out, int out_size)
{
    // metadata order: t (1), state (B*6), control_duty (B*3)
    const float* state = (const float*)d_in[1];
    const float* ctrl  = (const float*)d_in[2];
    float* out = (float*)d_out;
    int B = in_sizes[1] / 6;

    if ((B & 3) == 0) {
        int blocks = (B + ROWS_PER_BLK - 1) / ROWS_PER_BLK;
        mecanum_smem_kernel<<<blocks, THREADS>>>(
            (const float4*)state, (const float4*)ctrl, (float4*)out, B);
    } else {
        int threads = 256;
        int blocks = (B + threads - 1) / threads;
        mecanum1_kernel<<<blocks, threads>>>(state, ctrl, out, B);
    }
}